// round 10
// baseline (speedup 1.0000x reference)
#include <cuda_runtime.h>
#include <cuda_fp16.h>
#include <cstdint>

#define BB 32
#define LL 4096
#define EE 512
#define HH 512
#define AA 256

// ---------------- scratch (__device__ globals; no allocs allowed) ----------
__device__ float g_dec[BB * AA];                 // dec_attn + b_enc + b_dec
__device__ float g_scores[BB * LL];              // pre-softmax scores
__device__ float g_bm[BB * 32];                  // per-score-block max
__device__ float g_bs[BB * 32];                  // per-score-block sum-exp
__device__ float g_partial[BB * 32 * EE];        // exp-weighted feature partials
__device__ __half g_Bh[AA * EE];                 // W_enc^T fp16, [a][k] K-major

// ---------------- family-portable PTX helpers ------------------------------
__device__ __forceinline__ uint32_t smem_u32(const void* p) {
    uint32_t a;
    asm("{ .reg .u64 t; cvta.to.shared.u64 t, %1; cvt.u32.u64 %0, t; }"
        : "=r"(a) : "l"(p));
    return a;
}
__device__ __forceinline__ uint32_t pack_h2(float lo, float hi) {
    uint32_t r;
    asm("cvt.rn.f16x2.f32 %0, %1, %2;" : "=r"(r) : "f"(hi), "f"(lo));
    return r;
}
#define LDSM4(r, addr)                                                        \
    asm volatile("ldmatrix.sync.aligned.m8n8.x4.shared.b16 {%0,%1,%2,%3}, [%4];" \
        : "=r"((r)[0]), "=r"((r)[1]), "=r"((r)[2]), "=r"((r)[3]) : "r"(addr))

#define MMA_F16(d, a, b0, b1)                                                 \
    asm volatile("mma.sync.aligned.m16n8k16.row.col.f32.f16.f16.f32 "         \
        "{%0,%1,%2,%3}, {%4,%5,%6,%7}, {%8,%9}, {%0,%1,%2,%3};"               \
        : "+f"((d)[0]), "+f"((d)[1]), "+f"((d)[2]), "+f"((d)[3])              \
        : "r"((a)[0]), "r"((a)[1]), "r"((a)[2]), "r"((a)[3]),                 \
          "r"(b0), "r"(b1))

#define CP16(dst, src)                                                        \
    asm volatile("cp.async.cg.shared.global [%0], [%1], 16;"                  \
        :: "r"(dst), "l"(src) : "memory")
#define CP_COMMIT() asm volatile("cp.async.commit_group;" ::: "memory")
#define CP_WAIT0()  asm volatile("cp.async.wait_group 0;" ::: "memory")
#define CP_WAIT1()  asm volatile("cp.async.wait_group 1;" ::: "memory")

// ---------------- SMEM layout (bytes) ---------------------------------------
// XOR-swizzled tiles (granule = 16B = 8 halfs): addr = row*128 + ((g^(row&7))<<4)
// A: 8 resident chunks of [128 rows x 64 halfs] = 8 x 16 KB
// B: 3-slot ring of [256 rows x 64 halfs]      = 3 x 32 KB
#define A_SLOT 16384
#define OFF_B  131072
#define B_SLOT 32768
#define SMEM_BYTES 229376    // 224 KB (<227 KB opt-in), 1 CTA/SM
// post-mainloop scratch lives in the dead B region:
#define OFF_SRED OFF_B             // 128*4 f32
#define OFF_ST   (OFF_B + 2048)    // 17 f32
#define OFF_EW   (OFF_B + 2304)    // 128 f32 exp weights

// ---------------------------------------------------------------------------
// setup: blocks [0,512) convert W_enc -> fp16 K-major; blocks [512,544) dec
// ---------------------------------------------------------------------------
__global__ __launch_bounds__(256) void setup_kernel(
    const float* __restrict__ W_enc, const float* __restrict__ dh,
    const float* __restrict__ W_dec, const float* __restrict__ b_enc,
    const float* __restrict__ b_dec)
{
    if (blockIdx.x < 512) {
        int idx = blockIdx.x * 256 + threadIdx.x;   // [0, AA*EE)
        int a = idx >> 9, k = idx & 511;
        g_Bh[idx] = __float2half_rn(W_enc[(size_t)k * AA + a]);
    } else {
        int b = blockIdx.x - 512, a = threadIdx.x;
        __shared__ float sh[HH];
        for (int h = threadIdx.x; h < HH; h += 256) sh[h] = dh[b * HH + h];
        __syncthreads();
        float acc = 0.f;
#pragma unroll 8
        for (int h = 0; h < HH; h++) acc = fmaf(sh[h], W_dec[h * AA + a], acc);
        g_dec[b * AA + a] = acc + b_enc[a] + b_dec[a];
    }
}

// ---------------------------------------------------------------------------
// Fused score GEMM + softmax stats + in-SMEM exp-weighted feature partial.
// A tile (fp16, all 8 K-chunks) stays resident; B triple-buffered cp.async.
// ---------------------------------------------------------------------------
__global__ __launch_bounds__(512, 1) void score_kernel(
    const float* __restrict__ features,
    const float* __restrict__ W_v,
    const float* __restrict__ b_v)
{
    extern __shared__ __align__(16) char smem[];
    const uint32_t sb = smem_u32(smem);

    const int tid  = threadIdx.x;
    const int lane = tid & 31;
    const int wid  = tid >> 5;
    const int warp_m = wid & 3;
    const int warp_n = wid >> 2;
    const int row0 = blockIdx.x * 128;
    const int b    = row0 >> 12;

    const int m_base = warp_m * 32;
    const int n_base = warp_n * 64;

    // ldmatrix lane-constant terms (XOR swizzle)
    const int arow = m_base + (lane & 15);       // A row (mt adds 16: &7 invariant)
    const int arx  = arow & 7;
    const int ag0  = lane >> 4;                  // A granule base
    const int brow = n_base + (lane >> 4) * 8 + (lane & 7);  // B row (ntp adds 16)
    const int brx  = lane & 7;
    const int bg0  = (lane >> 3) & 1;            // B granule base

    float d[2][8][4];
#pragma unroll
    for (int mt = 0; mt < 2; mt++)
#pragma unroll
        for (int nt = 0; nt < 8; nt++)
#pragma unroll
            for (int q = 0; q < 4; q++) d[mt][nt][q] = 0.f;

    // A load/convert: thread covers row tid/4, 16 floats at col (tid&3)*16
    const int ar = tid >> 2, aq = tid & 3;
    const int arx_s = ar & 7;
    const float4* f4 = (const float4*)features +
                       ((size_t)row0 + ar) * 128 + aq * 4;

    float4 fr[4];

    auto cp_b = [&](int chunk) {
        const uint32_t base = sb + OFF_B + (uint32_t)(chunk % 3) * B_SLOT;
        const int k0 = chunk * 64;
#pragma unroll
        for (int i = 0; i < 4; i++) {
            int idx = tid + i * 512;            // [0,2048)
            int a = idx >> 3, seg = idx & 7;
            uint32_t dst = base + (uint32_t)(a * 128 + (((seg) ^ (a & 7)) << 4));
            CP16(dst, g_Bh + (size_t)a * EE + k0 + seg * 8);
        }
        CP_COMMIT();
    };
    auto lda = [&](int chunk) {
#pragma unroll
        for (int j = 0; j < 4; j++) fr[j] = f4[chunk * 16 + j];
    };
    auto sts_a = [&](int chunk) {
        char* base = smem + chunk * A_SLOT + ar * 128;
        *(uint4*)(base + ((((2 * aq + 0) ^ arx_s)) << 4)) = make_uint4(
            pack_h2(fr[0].x, fr[0].y), pack_h2(fr[0].z, fr[0].w),
            pack_h2(fr[1].x, fr[1].y), pack_h2(fr[1].z, fr[1].w));
        *(uint4*)(base + ((((2 * aq + 1) ^ arx_s)) << 4)) = make_uint4(
            pack_h2(fr[2].x, fr[2].y), pack_h2(fr[2].z, fr[2].w),
            pack_h2(fr[3].x, fr[3].y), pack_h2(fr[3].z, fr[3].w));
    };

    // prologue: B(0),B(1) in flight; A(0) staged; A(1) in regs
    cp_b(0);
    cp_b(1);
    lda(0); sts_a(0);
    lda(1);

    for (int c = 0; c < 8; c++) {
        if (c < 7) sts_a(c + 1);           // unique A slot c+1
        if (c < 7) CP_WAIT1(); else CP_WAIT0();   // B(c) complete
        __syncthreads();                   // A(c)+B(c) visible; prev compute done
        if (c < 6) {
            cp_b(c + 2);                   // B slot (c+2)%3: readers done pre-bar
            lda(c + 2);
        }

        const uint32_t aBase = sb + (uint32_t)c * A_SLOT;
        const uint32_t bBase = sb + OFF_B + (uint32_t)(c % 3) * B_SLOT;
#pragma unroll
        for (int ks = 0; ks < 4; ks++) {
            uint32_t ah[2][4];
#pragma unroll
            for (int mt = 0; mt < 2; mt++) {
                int g = ag0 + ks * 2;
                LDSM4(ah[mt], aBase + (uint32_t)((arow + mt * 16) * 128 +
                                                 ((g ^ arx) << 4)));
            }
#pragma unroll
            for (int ntp = 0; ntp < 4; ntp++) {
                uint32_t bh[4];
                int g = bg0 + ks * 2;
                LDSM4(bh, bBase + (uint32_t)((brow + ntp * 16) * 128 +
                                             ((g ^ brx) << 4)));
#pragma unroll
                for (int mt = 0; mt < 2; mt++)
#pragma unroll
                    for (int t = 0; t < 2; t++)
                        MMA_F16(d[mt][ntp * 2 + t], ah[mt],
                                bh[2 * t], bh[2 * t + 1]);
            }
        }
    }

    // ---- epilogue: + dec, relu, dot W_v (dec/W_v from global — L2-hot) -----
    __syncthreads();                       // all B reads done; reuse B region
    float* sred = (float*)(smem + OFF_SRED);
    float* st   = (float*)(smem + OFF_ST);
    float* ews  = (float*)(smem + OFF_EW);

#pragma unroll
    for (int mt = 0; mt < 2; mt++) {
        float s0 = 0.f, s1 = 0.f;
#pragma unroll
        for (int nt = 0; nt < 8; nt++) {
            int c0 = n_base + nt * 8 + (lane & 3) * 2;
            float e0 = __ldg(&g_dec[b * AA + c0]);
            float e1 = __ldg(&g_dec[b * AA + c0 + 1]);
            float w0 = __ldg(&W_v[c0]);
            float w1 = __ldg(&W_v[c0 + 1]);
            s0 = fmaf(fmaxf(d[mt][nt][0] + e0, 0.f), w0, s0);
            s0 = fmaf(fmaxf(d[mt][nt][1] + e1, 0.f), w1, s0);
            s1 = fmaf(fmaxf(d[mt][nt][2] + e0, 0.f), w0, s1);
            s1 = fmaf(fmaxf(d[mt][nt][3] + e1, 0.f), w1, s1);
        }
        s0 += __shfl_xor_sync(~0u, s0, 1);
        s0 += __shfl_xor_sync(~0u, s0, 2);
        s1 += __shfl_xor_sync(~0u, s1, 1);
        s1 += __shfl_xor_sync(~0u, s1, 2);
        if ((lane & 3) == 0) {
            int r = m_base + mt * 16 + (lane >> 2);
            sred[r * 4 + warp_n] = s0;
            sred[(r + 8) * 4 + warp_n] = s1;
        }
    }
    __syncthreads();

    float s = -1e30f;
    if (tid < 128) {
        s = sred[tid * 4] + sred[tid * 4 + 1] +
            sred[tid * 4 + 2] + sred[tid * 4 + 3] + __ldg(b_v);
        g_scores[row0 + tid] = s;
    }
    __syncthreads();

    // ---- block softmax stats + exp weights --------------------------------
    float m = s;
#pragma unroll
    for (int o = 16; o; o >>= 1) m = fmaxf(m, __shfl_xor_sync(~0u, m, o));
    if (lane == 0) st[wid] = m;
    __syncthreads();
    if (tid == 0) {
        float M = st[0];
#pragma unroll
        for (int i = 1; i < 16; i++) M = fmaxf(M, st[i]);
        st[16] = M;
    }
    __syncthreads();
    const float M = st[16];
    float e = (tid < 128) ? __expf(s - M) : 0.f;
    if (tid < 128) ews[tid] = e;
#pragma unroll
    for (int o = 16; o; o >>= 1) e += __shfl_xor_sync(~0u, e, o);
    __syncthreads();
    if (lane == 0) st[wid] = e;
    __syncthreads();
    if (tid == 0) {
        float S = 0.f;
#pragma unroll
        for (int i = 0; i < 16; i++) S += st[i];
        g_bm[blockIdx.x] = M;
        g_bs[blockIdx.x] = S;
    }
    __syncthreads();                       // ews visible to all

    // ---- in-SMEM exp-weighted feature partial: P[e] = sum_l ew[l]*f16[l][e]
    {
        const int eidx = tid;                       // one E column per thread
        const int ch = eidx >> 6;
        const int cg = (eidx & 63) >> 3;
        const uint32_t ebase = (uint32_t)(ch * A_SLOT + (eidx & 7) * 2);
        float acc = 0.f;
#pragma unroll 8
        for (int l = 0; l < 128; l++) {
            const __half* hp = (const __half*)(smem + ebase + l * 128 +
                                               ((cg ^ (l & 7)) << 4));
            acc = fmaf(__half2float(*hp), ews[l], acc);
        }
        g_partial[(size_t)blockIdx.x * EE + eidx] = acc;
    }
}

// ---------------------------------------------------------------------------
// finalize: per batch, combine 32 block partials + stats -> output & attn
// ---------------------------------------------------------------------------
__global__ __launch_bounds__(512) void finalize_kernel(
    float* __restrict__ out, float* __restrict__ attn)
{
    const int b = blockIdx.x;
    const int tid = threadIdx.x;
    __shared__ float scale[32];
    __shared__ float MS[2];

    if (tid < 32) {
        float m = g_bm[b * 32 + tid];
        float sl = g_bs[b * 32 + tid];
        float M = m;
#pragma unroll
        for (int o = 16; o; o >>= 1) M = fmaxf(M, __shfl_xor_sync(~0u, M, o));
        float S = sl * __expf(m - M);
#pragma unroll
        for (int o = 16; o; o >>= 1) S += __shfl_xor_sync(~0u, S, o);
        if (tid == 0) { MS[0] = M; MS[1] = S; }
    }
    __syncthreads();
    const float M = MS[0];
    const float invS = 1.f / MS[1];
    if (tid < 32) scale[tid] = __expf(g_bm[b * 32 + tid] - M) * invS;
    __syncthreads();

    // output[b, e]
    float acc = 0.f;
#pragma unroll
    for (int blk = 0; blk < 32; blk++)
        acc = fmaf(g_partial[(size_t)(b * 32 + blk) * EE + tid], scale[blk], acc);
    out[b * EE + tid] = acc;

    // attn[b, l]
    const float* sc = g_scores + (size_t)b * LL;
    float* w = attn + (size_t)b * LL;
    for (int l = tid; l < LL; l += 512)
        w[l] = __expf(sc[l] - M) * invS;
}

// ---------------------------------------------------------------------------
extern "C" void kernel_launch(void* const* d_in, const int* in_sizes, int n_in,
                              void* d_out, int out_size)
{
    const float* features = (const float*)d_in[0];
    const float* dh       = (const float*)d_in[1];
    const float* W_enc    = (const float*)d_in[2];
    const float* b_enc    = (const float*)d_in[3];
    const float* W_dec    = (const float*)d_in[4];
    const float* b_dec    = (const float*)d_in[5];
    const float* W_v      = (const float*)d_in[6];
    const float* b_v      = (const float*)d_in[7];

    float* out  = (float*)d_out;        // [B,E]
    float* attn = out + BB * EE;        // [B,L]

    cudaFuncSetAttribute(score_kernel,
                         cudaFuncAttributeMaxDynamicSharedMemorySize,
                         SMEM_BYTES);

    setup_kernel<<<544, 256>>>(W_enc, dh, W_dec, b_enc, b_dec);
    score_kernel<<<(BB * LL) / 128, 512, SMEM_BYTES>>>(features, W_v, b_v);
    finalize_kernel<<<BB, 512>>>(out, attn);
}

// round 11
// speedup vs baseline: 1.0622x; 1.0622x over previous
#include <cuda_runtime.h>
#include <cuda_fp16.h>
#include <cstdint>

#define BB 32
#define LL 4096
#define EE 512
#define HH 512
#define AA 256

// ---------------- scratch (__device__ globals; no allocs allowed) ----------
__device__ float g_dec[BB * AA];                 // dec_attn + b_enc + b_dec
__device__ float g_scores[BB * LL];              // pre-softmax scores
__device__ float g_bm[BB * 32];                  // per-score-block max
__device__ float g_bs[BB * 32];                  // per-score-block sum-exp
__device__ float g_partial[BB * 64 * EE];        // weighted-sum partials
__device__ __half g_Bh[AA * EE];                 // W_enc^T fp16, [a][k] K-major

// ---------------- family-portable PTX helpers ------------------------------
__device__ __forceinline__ uint32_t smem_u32(const void* p) {
    uint32_t a;
    asm("{ .reg .u64 t; cvta.to.shared.u64 t, %1; cvt.u32.u64 %0, t; }"
        : "=r"(a) : "l"(p));
    return a;
}
__device__ __forceinline__ uint32_t pack_h2(float lo, float hi) {
    uint32_t r;
    asm("cvt.rn.f16x2.f32 %0, %1, %2;" : "=r"(r) : "f"(hi), "f"(lo));
    return r;
}
#define LDSM4(r, addr)                                                        \
    asm volatile("ldmatrix.sync.aligned.m8n8.x4.shared.b16 {%0,%1,%2,%3}, [%4];" \
        : "=r"((r)[0]), "=r"((r)[1]), "=r"((r)[2]), "=r"((r)[3]) : "r"(addr))

#define MMA_F16(d, a, b0, b1)                                                 \
    asm volatile("mma.sync.aligned.m16n8k16.row.col.f32.f16.f16.f32 "         \
        "{%0,%1,%2,%3}, {%4,%5,%6,%7}, {%8,%9}, {%0,%1,%2,%3};"               \
        : "+f"((d)[0]), "+f"((d)[1]), "+f"((d)[2]), "+f"((d)[3])              \
        : "r"((a)[0]), "r"((a)[1]), "r"((a)[2]), "r"((a)[3]),                 \
          "r"(b0), "r"(b1))

#define CP16(dst, src)                                                        \
    asm volatile("cp.async.cg.shared.global [%0], [%1], 16;"                  \
        :: "r"(dst), "l"(src) : "memory")
#define CP_COMMIT() asm volatile("cp.async.commit_group;" ::: "memory")
#define CP_WAIT0()  asm volatile("cp.async.wait_group 0;" ::: "memory")
#define CP_WAIT1()  asm volatile("cp.async.wait_group 1;" ::: "memory")

// ---------------- SMEM layout for score kernel (bytes) ---------------------
#define SA 72                // padded k-stride (halfs) -> conflict-free ldmatrix
#define OFF_DEC 0            // 256 f32
#define OFF_WV  1024         // 256 f32
#define OFF_RED 2048         // reduce + stats scratch (2048 B)
#define OFF_A   4096         // A ring: 3 x (128 x SA halfs)
#define A_STRIDE 18432
#define OFF_B   59392        // B ring: 3 x (256 x SA halfs)
#define B_STRIDE 36864
#define SMEM_BYTES 169984    // 166 KB, 1 CTA/SM

// ---------------------------------------------------------------------------
// setup: blocks [0,32) tiled transpose W_enc -> fp16 K-major (coalesced);
//        blocks [32,64) dec projection.
// ---------------------------------------------------------------------------
__global__ __launch_bounds__(256) void setup_kernel(
    const float* __restrict__ W_enc, const float* __restrict__ dh,
    const float* __restrict__ W_dec, const float* __restrict__ b_enc,
    const float* __restrict__ b_dec)
{
    if (blockIdx.x < 32) {
        // 64x64 tile transpose: W_enc[k][a] (row-major) -> g_Bh[a][k]
        __shared__ __half sh[64][65];
        const int kt = blockIdx.x >> 2;          // 8 k-tiles
        const int at = blockIdx.x & 3;           // 4 a-tiles
        const int k0 = kt * 64, a0 = at * 64;
#pragma unroll
        for (int i = 0; i < 16; i++) {
            int idx = threadIdx.x + i * 256;     // [0,4096)
            int r = idx >> 6, ca = idx & 63;     // coalesced read: consec a
            sh[ca][r] = __float2half_rn(W_enc[(size_t)(k0 + r) * AA + a0 + ca]);
        }
        __syncthreads();
#pragma unroll
        for (int i = 0; i < 16; i++) {
            int idx = threadIdx.x + i * 256;
            int arr = idx >> 6, ck = idx & 63;   // coalesced write: consec k
            g_Bh[(size_t)(a0 + arr) * EE + k0 + ck] = sh[arr][ck];
        }
    } else {
        int b = blockIdx.x - 32, a = threadIdx.x;
        __shared__ float shh[HH];
        for (int h = threadIdx.x; h < HH; h += 256) shh[h] = dh[b * HH + h];
        __syncthreads();
        float acc = 0.f;
#pragma unroll 8
        for (int h = 0; h < HH; h++) acc = fmaf(shh[h], W_dec[h * AA + a], acc);
        g_dec[b * AA + a] = acc + b_enc[a] + b_dec[a];
    }
}

// ---------------------------------------------------------------------------
// Fused score GEMM, single-term fp16, f32 accum.
// Triple-buffered A & B rings (mod 3) -> ONE __syncthreads per K-chunk.
// ---------------------------------------------------------------------------
__global__ __launch_bounds__(512, 1) void score_kernel(
    const float* __restrict__ features,
    const float* __restrict__ W_v,
    const float* __restrict__ b_v)
{
    extern __shared__ __align__(16) char smem[];
    const uint32_t sb = smem_u32(smem);

    const int tid  = threadIdx.x;
    const int lane = tid & 31;
    const int wid  = tid >> 5;
    const int warp_m = wid & 3;
    const int warp_n = wid >> 2;
    const int row0 = blockIdx.x * 128;
    const int b    = row0 >> 12;

    float* sdec = (float*)(smem + OFF_DEC);
    float* swv  = (float*)(smem + OFF_WV);
    float* sred = (float*)(smem + OFF_RED);
    if (tid < 256) {
        sdec[tid] = g_dec[b * AA + tid];
        swv[tid]  = W_v[tid];
    }

    const int m_base = warp_m * 32;
    const int n_base = warp_n * 64;
    const uint32_t aoff =
        (uint32_t)((m_base + (lane & 15)) * SA + (lane >> 4) * 8) * 2;
    const uint32_t boff =
        (uint32_t)((n_base + (lane >> 4) * 8 + (lane & 7)) * SA +
                   ((lane >> 3) & 1) * 8) * 2;

    float d[2][8][4];
#pragma unroll
    for (int mt = 0; mt < 2; mt++)
#pragma unroll
        for (int nt = 0; nt < 8; nt++)
#pragma unroll
            for (int q = 0; q < 4; q++) d[mt][nt][q] = 0.f;

    // A prefetch: thread covers row tid/4, 16 floats at col (tid&3)*16
    const int ar = tid >> 2, aq = tid & 3;
    const float4* f4 = (const float4*)features +
                       ((size_t)row0 + ar) * 128 + aq * 4;
    const uint32_t a_sts = (uint32_t)(ar * SA + aq * 16) * 2;

    float4 fr[4];

    auto cp_b = [&](int chunk) {
        const uint32_t base = sb + OFF_B + (uint32_t)(chunk % 3) * B_STRIDE;
        const int k0 = chunk * 64;
#pragma unroll
        for (int i = 0; i < 4; i++) {
            int idx = tid + i * 512;            // [0,2048)
            int a = idx >> 3, seg = idx & 7;
            uint32_t dst = base + (uint32_t)(a * SA + seg * 8) * 2;
            CP16(dst, g_Bh + (size_t)a * EE + k0 + seg * 8);
        }
        CP_COMMIT();
    };
    auto lda = [&](int chunk) {
#pragma unroll
        for (int j = 0; j < 4; j++) fr[j] = f4[chunk * 16 + j];
    };
    auto sts_a = [&](int chunk) {
        char* dst = smem + OFF_A + (chunk % 3) * A_STRIDE + a_sts;
        *(uint4*)dst = make_uint4(
            pack_h2(fr[0].x, fr[0].y), pack_h2(fr[0].z, fr[0].w),
            pack_h2(fr[1].x, fr[1].y), pack_h2(fr[1].z, fr[1].w));
        *(uint4*)(dst + 16) = make_uint4(
            pack_h2(fr[2].x, fr[2].y), pack_h2(fr[2].z, fr[2].w),
            pack_h2(fr[3].x, fr[3].y), pack_h2(fr[3].z, fr[3].w));
    };

    // prologue: B(0),B(1) in flight; A(0) staged; A(1) in regs
    cp_b(0);
    cp_b(1);
    lda(0); sts_a(0);
    lda(1);

    for (int c = 0; c < 8; c++) {
        if (c < 7) sts_a(c + 1);           // A ring slot (c+1)%3 — disjoint
        if (c < 7) CP_WAIT1(); else CP_WAIT0();   // B(c) complete
        __syncthreads();                   // A(c)+B(c) visible; prev compute done
        if (c < 6) {
            cp_b(c + 2);                   // B slot (c+2)%3 — readers past bar
            lda(c + 2);
        }

        const uint32_t aBase = sb + OFF_A + (uint32_t)(c % 3) * A_STRIDE + aoff;
        const uint32_t bBase = sb + OFF_B + (uint32_t)(c % 3) * B_STRIDE;
#pragma unroll
        for (int ks = 0; ks < 4; ks++) {
            uint32_t ah[2][4];
#pragma unroll
            for (int mt = 0; mt < 2; mt++)
                LDSM4(ah[mt], aBase + (uint32_t)(mt * 16 * SA + ks * 16) * 2);
#pragma unroll
            for (int ntp = 0; ntp < 4; ntp++) {
                uint32_t bh[4];
                LDSM4(bh, bBase + boff +
                          (uint32_t)(ntp * 16 * SA + ks * 16) * 2);
#pragma unroll
                for (int mt = 0; mt < 2; mt++)
#pragma unroll
                    for (int t = 0; t < 2; t++)
                        MMA_F16(d[mt][ntp * 2 + t], ah[mt],
                                bh[2 * t], bh[2 * t + 1]);
            }
        }
    }

    // ---- epilogue: + dec, relu, dot W_v; quad shuffle + 4-way smem reduce --
    __syncthreads();                       // all MMAs done before sred reuse
#pragma unroll
    for (int mt = 0; mt < 2; mt++) {
        float s0 = 0.f, s1 = 0.f;
#pragma unroll
        for (int nt = 0; nt < 8; nt++) {
            int c0 = n_base + nt * 8 + (lane & 3) * 2;
            float e0 = sdec[c0], e1 = sdec[c0 + 1];
            float w0 = swv[c0], w1 = swv[c0 + 1];
            s0 = fmaf(fmaxf(d[mt][nt][0] + e0, 0.f), w0, s0);
            s0 = fmaf(fmaxf(d[mt][nt][1] + e1, 0.f), w1, s0);
            s1 = fmaf(fmaxf(d[mt][nt][2] + e0, 0.f), w0, s1);
            s1 = fmaf(fmaxf(d[mt][nt][3] + e1, 0.f), w1, s1);
        }
        s0 += __shfl_xor_sync(~0u, s0, 1);
        s0 += __shfl_xor_sync(~0u, s0, 2);
        s1 += __shfl_xor_sync(~0u, s1, 1);
        s1 += __shfl_xor_sync(~0u, s1, 2);
        if ((lane & 3) == 0) {
            int r = m_base + mt * 16 + (lane >> 2);
            sred[r * 4 + warp_n] = s0;
            sred[(r + 8) * 4 + warp_n] = s1;
        }
    }
    __syncthreads();

    float s = -1e30f;
    if (tid < 128) {
        s = sred[tid * 4] + sred[tid * 4 + 1] +
            sred[tid * 4 + 2] + sred[tid * 4 + 3] + b_v[0];
        g_scores[row0 + tid] = s;
    }
    __syncthreads();

    // ---- per-block softmax stats: max + sum-exp over the 128 scores -------
    float* st = sred;                       // reuse
    float m = s;
#pragma unroll
    for (int o = 16; o; o >>= 1) m = fmaxf(m, __shfl_xor_sync(~0u, m, o));
    if (lane == 0) st[wid] = m;
    __syncthreads();
    if (tid == 0) {
        float M = st[0];
#pragma unroll
        for (int i = 1; i < 16; i++) M = fmaxf(M, st[i]);
        st[16] = M;
    }
    __syncthreads();
    const float M = st[16];
    float e = (tid < 128) ? __expf(s - M) : 0.f;
#pragma unroll
    for (int o = 16; o; o >>= 1) e += __shfl_xor_sync(~0u, e, o);
    __syncthreads();
    if (lane == 0) st[wid] = e;
    __syncthreads();
    if (tid == 0) {
        float S = 0.f;
#pragma unroll
        for (int i = 0; i < 16; i++) S += st[i];
        g_bm[blockIdx.x] = M;
        g_bs[blockIdx.x] = S;
    }
}

// ---------------------------------------------------------------------------
// wsum_attn: combine block stats -> exact softmax; write attn weights to
// d_out tail; partial weighted sums (64 chunks x 64 L-rows, 8 accumulators).
// ---------------------------------------------------------------------------
__global__ __launch_bounds__(512) void wsum_attn(
    const float* __restrict__ features, float* __restrict__ attn)
{
    int b = blockIdx.y, chunk = blockIdx.x;
    __shared__ float sw[64];
    __shared__ float MS[2];

    if (threadIdx.x < 32) {
        float m = g_bm[b * 32 + threadIdx.x];
        float sloc = g_bs[b * 32 + threadIdx.x];
        float M = m;
#pragma unroll
        for (int o = 16; o; o >>= 1) M = fmaxf(M, __shfl_xor_sync(~0u, M, o));
        float S = sloc * __expf(m - M);
#pragma unroll
        for (int o = 16; o; o >>= 1) S += __shfl_xor_sync(~0u, S, o);
        if (threadIdx.x == 0) { MS[0] = M; MS[1] = S; }
    }
    __syncthreads();
    if (threadIdx.x < 64) {
        int l = chunk * 64 + threadIdx.x;
        float w = __expf(g_scores[(size_t)b * LL + l] - MS[0]) / MS[1];
        sw[threadIdx.x] = w;
        attn[(size_t)b * LL + l] = w;
    }
    __syncthreads();

    const float* f = features + ((size_t)b * LL + (size_t)chunk * 64) * EE
                     + threadIdx.x;
    float a0 = 0.f, a1 = 0.f, a2 = 0.f, a3 = 0.f;
    float a4 = 0.f, a5 = 0.f, a6 = 0.f, a7 = 0.f;
#pragma unroll
    for (int i = 0; i < 64; i += 8) {
        float v0 = __ldcs(&f[(size_t)(i + 0) * EE]);
        float v1 = __ldcs(&f[(size_t)(i + 1) * EE]);
        float v2 = __ldcs(&f[(size_t)(i + 2) * EE]);
        float v3 = __ldcs(&f[(size_t)(i + 3) * EE]);
        float v4 = __ldcs(&f[(size_t)(i + 4) * EE]);
        float v5 = __ldcs(&f[(size_t)(i + 5) * EE]);
        float v6 = __ldcs(&f[(size_t)(i + 6) * EE]);
        float v7 = __ldcs(&f[(size_t)(i + 7) * EE]);
        a0 = fmaf(v0, sw[i + 0], a0);
        a1 = fmaf(v1, sw[i + 1], a1);
        a2 = fmaf(v2, sw[i + 2], a2);
        a3 = fmaf(v3, sw[i + 3], a3);
        a4 = fmaf(v4, sw[i + 4], a4);
        a5 = fmaf(v5, sw[i + 5], a5);
        a6 = fmaf(v6, sw[i + 6], a6);
        a7 = fmaf(v7, sw[i + 7], a7);
    }
    g_partial[((size_t)b * 64 + chunk) * EE + threadIdx.x] =
        ((a0 + a1) + (a2 + a3)) + ((a4 + a5) + (a6 + a7));
}

__global__ __launch_bounds__(128) void wsum_reduce(float* __restrict__ out)
{
    int idx = blockIdx.x * 128 + threadIdx.x;  // [0, B*E)
    int b = idx / EE, e = idx - b * EE;
    float acc = 0.f;
#pragma unroll
    for (int c = 0; c < 64; c++)
        acc += g_partial[((size_t)b * 64 + c) * EE + e];
    out[idx] = acc;
}

// ---------------------------------------------------------------------------
extern "C" void kernel_launch(void* const* d_in, const int* in_sizes, int n_in,
                              void* d_out, int out_size)
{
    const float* features = (const float*)d_in[0];
    const float* dh       = (const float*)d_in[1];
    const float* W_enc    = (const float*)d_in[2];
    const float* b_enc    = (const float*)d_in[3];
    const float* W_dec    = (const float*)d_in[4];
    const float* b_dec    = (const float*)d_in[5];
    const float* W_v      = (const float*)d_in[6];
    const float* b_v      = (const float*)d_in[7];

    float* out  = (float*)d_out;        // [B,E]
    float* attn = out + BB * EE;        // [B,L]

    cudaFuncSetAttribute(score_kernel,
                         cudaFuncAttributeMaxDynamicSharedMemorySize,
                         SMEM_BYTES);

    setup_kernel<<<64, 256>>>(W_enc, dh, W_dec, b_enc, b_dec);
    score_kernel<<<(BB * LL) / 128, 512, SMEM_BYTES>>>(features, W_v, b_v);
    wsum_attn<<<dim3(64, BB), 512>>>(features, attn);
    wsum_reduce<<<(BB * EE) / 128, 128>>>(out);
}

// round 12
// speedup vs baseline: 1.0722x; 1.0095x over previous
#include <cuda_runtime.h>
#include <cuda_fp16.h>
#include <cstdint>

#define BB 32
#define LL 4096
#define EE 512
#define HH 512
#define AA 256

// ---------------- scratch (__device__ globals; no allocs allowed) ----------
__device__ float g_dec[BB * AA];                 // dec_attn + b_enc + b_dec
__device__ float g_scores[BB * LL];              // pre-softmax scores
__device__ float g_bm[BB * 32];                  // per-score-block max
__device__ float g_bs[BB * 32];                  // per-score-block sum-exp
__device__ float g_partial[BB * 32 * EE];        // exp-weighted feature partials
__device__ __half g_Bh[AA * EE];                 // W_enc^T fp16, [a][k] K-major

// ---------------- family-portable PTX helpers ------------------------------
__device__ __forceinline__ uint32_t smem_u32(const void* p) {
    uint32_t a;
    asm("{ .reg .u64 t; cvta.to.shared.u64 t, %1; cvt.u32.u64 %0, t; }"
        : "=r"(a) : "l"(p));
    return a;
}
__device__ __forceinline__ uint32_t pack_h2(float lo, float hi) {
    uint32_t r;
    asm("cvt.rn.f16x2.f32 %0, %1, %2;" : "=r"(r) : "f"(hi), "f"(lo));
    return r;
}
#define LDSM4(r, addr)                                                        \
    asm volatile("ldmatrix.sync.aligned.m8n8.x4.shared.b16 {%0,%1,%2,%3}, [%4];" \
        : "=r"((r)[0]), "=r"((r)[1]), "=r"((r)[2]), "=r"((r)[3]) : "r"(addr))

#define MMA_F16(d, a, b0, b1)                                                 \
    asm volatile("mma.sync.aligned.m16n8k16.row.col.f32.f16.f16.f32 "         \
        "{%0,%1,%2,%3}, {%4,%5,%6,%7}, {%8,%9}, {%0,%1,%2,%3};"               \
        : "+f"((d)[0]), "+f"((d)[1]), "+f"((d)[2]), "+f"((d)[3])              \
        : "r"((a)[0]), "r"((a)[1]), "r"((a)[2]), "r"((a)[3]),                 \
          "r"(b0), "r"(b1))

#define CP16(dst, src)                                                        \
    asm volatile("cp.async.cg.shared.global [%0], [%1], 16;"                  \
        :: "r"(dst), "l"(src) : "memory")
#define CP_COMMIT() asm volatile("cp.async.commit_group;" ::: "memory")
#define CP_WAIT0()  asm volatile("cp.async.wait_group 0;" ::: "memory")
#define CP_WAIT1()  asm volatile("cp.async.wait_group 1;" ::: "memory")

// ---------------- SMEM layout (bytes) ---------------------------------------
// XOR swizzle, granule = 16B = 8 halfs: byte = row*128 + ((g ^ (row&7))<<4)
// A: 8 resident slots [128 x 64 halfs] = 8 x 16 KB = 128 KB  (at offset 0)
// B: 3-slot ring      [256 x 64 halfs] = 3 x 32 KB = 96 KB
#define A_SLOT 16384
#define OFF_B  131072
#define B_SLOT 32768
#define SMEM_BYTES 229376
// post-mainloop scratch overlays the dead B region:
#define OFF_SDEC OFF_B              // 256 f32
#define OFF_SWV  (OFF_B + 1024)     // 256 f32
#define OFF_SRED (OFF_B + 2048)     // 128*4 f32 (stats st reuses it)
#define OFF_EW   (OFF_B + 4096)     // 128 f32 exp weights
#define OFF_PSC  (OFF_B + 8192)     // 8 x 512 f32 colsum partials (16 KB)

// ---------------------------------------------------------------------------
// setup: blocks [0,32) tiled transpose W_enc -> fp16 K-major (coalesced);
//        blocks [32,64) dec projection.
// ---------------------------------------------------------------------------
__global__ __launch_bounds__(256) void setup_kernel(
    const float* __restrict__ W_enc, const float* __restrict__ dh,
    const float* __restrict__ W_dec, const float* __restrict__ b_enc,
    const float* __restrict__ b_dec)
{
    if (blockIdx.x < 32) {
        __shared__ __half sh[64][65];
        const int kt = blockIdx.x >> 2;
        const int at = blockIdx.x & 3;
        const int k0 = kt * 64, a0 = at * 64;
#pragma unroll
        for (int i = 0; i < 16; i++) {
            int idx = threadIdx.x + i * 256;
            int r = idx >> 6, ca = idx & 63;
            sh[ca][r] = __float2half_rn(W_enc[(size_t)(k0 + r) * AA + a0 + ca]);
        }
        __syncthreads();
#pragma unroll
        for (int i = 0; i < 16; i++) {
            int idx = threadIdx.x + i * 256;
            int arr = idx >> 6, ck = idx & 63;
            g_Bh[(size_t)(a0 + arr) * EE + k0 + ck] = sh[arr][ck];
        }
    } else {
        int b = blockIdx.x - 32, a = threadIdx.x;
        __shared__ float shh[HH];
        for (int h = threadIdx.x; h < HH; h += 256) shh[h] = dh[b * HH + h];
        __syncthreads();
        float acc = 0.f;
#pragma unroll 8
        for (int h = 0; h < HH; h++) acc = fmaf(shh[h], W_dec[h * AA + a], acc);
        g_dec[b * AA + a] = acc + b_enc[a] + b_dec[a];
    }
}

// ---------------------------------------------------------------------------
// Fused: score GEMM (fp16 mma.sync) + softmax stats + in-SMEM weighted sum.
// ---------------------------------------------------------------------------
__global__ __launch_bounds__(512, 1) void score_kernel(
    const float* __restrict__ features,
    const float* __restrict__ W_v,
    const float* __restrict__ b_v)
{
    extern __shared__ __align__(16) char smem[];
    const uint32_t sb = smem_u32(smem);

    const int tid  = threadIdx.x;
    const int lane = tid & 31;
    const int wid  = tid >> 5;
    const int warp_m = wid & 3;
    const int warp_n = wid >> 2;
    const int row0 = blockIdx.x * 128;
    const int b    = row0 >> 12;

    const int m_base = warp_m * 32;
    const int n_base = warp_n * 64;

    // ---- lane-constant swizzled ldmatrix offsets ---------------------------
    // A: row = m_base+(lane&15)+mt*16 ; granule = (lane>>4) + 2*ks
    const int arow = m_base + (lane & 15);
    const int arx  = arow & 7;                 // invariant under +16
    const uint32_t aA = (uint32_t)(arow * 128 +
                                   (((lane >> 4) ^ (arx & 1)) << 4));
    const int arxh = arx >> 1;                 // 0..3
    // B: row = n_base+(lane>>4)*8+(lane&7)+ntp*16 ; granule = ((lane>>3)&1)+2*ks
    const int brow = n_base + (lane >> 4) * 8 + (lane & 7);
    const int brx  = brow & 7;                 // == lane&7
    const uint32_t bB = (uint32_t)(brow * 128 +
                                   ((((lane >> 3) & 1) ^ (brx & 1)) << 4));
    const int brxh = brx >> 1;

    float d[2][8][4];
#pragma unroll
    for (int mt = 0; mt < 2; mt++)
#pragma unroll
        for (int nt = 0; nt < 8; nt++)
#pragma unroll
            for (int q = 0; q < 4; q++) d[mt][nt][q] = 0.f;

    // A global loads: thread -> row tid/4, 16 floats at col (tid&3)*16
    const int ar = tid >> 2, aq = tid & 3;
    const int arxs = ar & 7;
    const float4* f4 = (const float4*)features +
                       ((size_t)row0 + ar) * 128 + aq * 4;
    const uint32_t sts0 = (uint32_t)(ar * 128 + (((2 * aq) ^ arxs) << 4));
    const uint32_t sts1 = (uint32_t)(ar * 128 + (((2 * aq + 1) ^ arxs) << 4));

    float4 fr[4];

    auto cp_b = [&](int chunk) {
        const uint32_t base = sb + OFF_B + (uint32_t)(chunk % 3) * B_SLOT;
        const int k0 = chunk * 64;
#pragma unroll
        for (int i = 0; i < 4; i++) {
            int idx = tid + i * 512;            // [0,2048)
            int a = idx >> 3, seg = idx & 7;
            uint32_t dst = base + (uint32_t)(a * 128 + ((seg ^ (a & 7)) << 4));
            CP16(dst, g_Bh + (size_t)a * EE + k0 + seg * 8);
        }
        CP_COMMIT();
    };
    auto lda = [&](int chunk) {
#pragma unroll
        for (int j = 0; j < 4; j++) fr[j] = f4[chunk * 16 + j];
    };
    auto sts_a = [&](int chunk) {
        char* base = smem + chunk * A_SLOT;
        *(uint4*)(base + sts0) = make_uint4(
            pack_h2(fr[0].x, fr[0].y), pack_h2(fr[0].z, fr[0].w),
            pack_h2(fr[1].x, fr[1].y), pack_h2(fr[1].z, fr[1].w));
        *(uint4*)(base + sts1) = make_uint4(
            pack_h2(fr[2].x, fr[2].y), pack_h2(fr[2].z, fr[2].w),
            pack_h2(fr[3].x, fr[3].y), pack_h2(fr[3].z, fr[3].w));
    };

    // prologue
    cp_b(0);
    cp_b(1);
    lda(0); sts_a(0);
    lda(1);

    for (int c = 0; c < 8; c++) {
        if (c < 7) sts_a(c + 1);           // unique resident slot c+1
        if (c < 7) CP_WAIT1(); else CP_WAIT0();
        __syncthreads();
        if (c < 6) {
            cp_b(c + 2);
            lda(c + 2);
        }

        const uint32_t aBase = sb + (uint32_t)c * A_SLOT + aA;
        const uint32_t bBase = sb + OFF_B + (uint32_t)(c % 3) * B_SLOT + bB;
#pragma unroll
        for (int ks = 0; ks < 4; ks++) {
            uint32_t ah[2][4];
#pragma unroll
            for (int mt = 0; mt < 2; mt++)
                LDSM4(ah[mt], aBase + (uint32_t)(mt * 2048 +
                                                 ((ks ^ arxh) << 5)));
#pragma unroll
            for (int ntp = 0; ntp < 4; ntp++) {
                uint32_t bh[4];
                LDSM4(bh, bBase + (uint32_t)(ntp * 2048 +
                                             ((ks ^ brxh) << 5)));
#pragma unroll
                for (int mt = 0; mt < 2; mt++)
#pragma unroll
                    for (int t = 0; t < 2; t++)
                        MMA_F16(d[mt][ntp * 2 + t], ah[mt],
                                bh[2 * t], bh[2 * t + 1]);
            }
        }
    }

    // ---- B region dead: stage dec/W_v into SMEM (1 ldg/thread) -------------
    __syncthreads();
    float* sdec = (float*)(smem + OFF_SDEC);
    float* swv  = (float*)(smem + OFF_SWV);
    float* sred = (float*)(smem + OFF_SRED);
    float* ews  = (float*)(smem + OFF_EW);
    float* psc  = (float*)(smem + OFF_PSC);
    if (tid < 256) sdec[tid] = g_dec[b * AA + tid];
    else           swv[tid - 256] = W_v[tid - 256];
    __syncthreads();

    // ---- epilogue: + dec, relu, dot W_v; quad shuffle + 4-way smem reduce --
#pragma unroll
    for (int mt = 0; mt < 2; mt++) {
        float s0 = 0.f, s1 = 0.f;
#pragma unroll
        for (int nt = 0; nt < 8; nt++) {
            int c0 = n_base + nt * 8 + (lane & 3) * 2;
            float e0 = sdec[c0], e1 = sdec[c0 + 1];
            float w0 = swv[c0], w1 = swv[c0 + 1];
            s0 = fmaf(fmaxf(d[mt][nt][0] + e0, 0.f), w0, s0);
            s0 = fmaf(fmaxf(d[mt][nt][1] + e1, 0.f), w1, s0);
            s1 = fmaf(fmaxf(d[mt][nt][2] + e0, 0.f), w0, s1);
            s1 = fmaf(fmaxf(d[mt][nt][3] + e1, 0.f), w1, s1);
        }
        s0 += __shfl_xor_sync(~0u, s0, 1);
        s0 += __shfl_xor_sync(~0u, s0, 2);
        s1 += __shfl_xor_sync(~0u, s1, 1);
        s1 += __shfl_xor_sync(~0u, s1, 2);
        if ((lane & 3) == 0) {
            int r = m_base + mt * 16 + (lane >> 2);
            sred[r * 4 + warp_n] = s0;
            sred[(r + 8) * 4 + warp_n] = s1;
        }
    }
    __syncthreads();

    float s = -1e30f;
    if (tid < 128) {
        s = sred[tid * 4] + sred[tid * 4 + 1] +
            sred[tid * 4 + 2] + sred[tid * 4 + 3] + __ldg(b_v);
        g_scores[row0 + tid] = s;
    }
    __syncthreads();

    // ---- block softmax stats + exp weights ---------------------------------
    float* st = sred;
    float m = s;
#pragma unroll
    for (int o = 16; o; o >>= 1) m = fmaxf(m, __shfl_xor_sync(~0u, m, o));
    if (lane == 0) st[wid] = m;
    __syncthreads();
    if (tid == 0) {
        float M = st[0];
#pragma unroll
        for (int i = 1; i < 16; i++) M = fmaxf(M, st[i]);
        st[16] = M;
    }
    __syncthreads();
    const float M = st[16];
    float e = (tid < 128) ? __expf(s - M) : 0.f;
    if (tid < 128) ews[tid] = e;
#pragma unroll
    for (int o = 16; o; o >>= 1) e += __shfl_xor_sync(~0u, e, o);
    __syncthreads();
    if (lane == 0) st[wid] = e;
    __syncthreads();
    if (tid == 0) {
        float S = 0.f;
#pragma unroll
        for (int i = 0; i < 16; i++) S += st[i];
        g_bm[blockIdx.x] = M;
        g_bs[blockIdx.x] = S;
    }
    __syncthreads();                       // ews visible

    // ---- vectorized in-SMEM weighted sum: P[e] = sum_l ews[l]*A16[l][e] ----
    {
        const int gcol = tid & 63;         // granule column (8 e's)
        const int sub  = tid >> 6;         // row octile 0..7
        const int ch   = gcol >> 3, gq = gcol & 7;
        char* abase = smem + ch * A_SLOT;
        float acc[8];
#pragma unroll
        for (int j = 0; j < 8; j++) acc[j] = 0.f;
#pragma unroll
        for (int i = 0; i < 16; i++) {
            int l = sub * 16 + i;
            uint4 v = *(uint4*)(abase + l * 128 + ((gq ^ (l & 7)) << 4));
            float w = ews[l];
            float2 p;
            p = __half22float2(*(__half2*)&v.x);
            acc[0] = fmaf(p.x, w, acc[0]); acc[1] = fmaf(p.y, w, acc[1]);
            p = __half22float2(*(__half2*)&v.y);
            acc[2] = fmaf(p.x, w, acc[2]); acc[3] = fmaf(p.y, w, acc[3]);
            p = __half22float2(*(__half2*)&v.z);
            acc[4] = fmaf(p.x, w, acc[4]); acc[5] = fmaf(p.y, w, acc[5]);
            p = __half22float2(*(__half2*)&v.w);
            acc[6] = fmaf(p.x, w, acc[6]); acc[7] = fmaf(p.y, w, acc[7]);
        }
#pragma unroll
        for (int j = 0; j < 8; j++)
            psc[sub * 512 + gcol * 8 + j] = acc[j];
    }
    __syncthreads();
    {
        float sum = 0.f;
#pragma unroll
        for (int sbi = 0; sbi < 8; sbi++)
            sum += psc[sbi * 512 + tid];
        g_partial[(size_t)blockIdx.x * EE + tid] = sum;
    }
}

// ---------------------------------------------------------------------------
// finalize: per batch, combine 32 block partials + stats -> output & attn
// ---------------------------------------------------------------------------
__global__ __launch_bounds__(512) void finalize_kernel(
    float* __restrict__ out, float* __restrict__ attn)
{
    const int b = blockIdx.x;
    const int tid = threadIdx.x;
    __shared__ float scale[32];
    __shared__ float MS[2];

    if (tid < 32) {
        float m = g_bm[b * 32 + tid];
        float sl = g_bs[b * 32 + tid];
        float M = m;
#pragma unroll
        for (int o = 16; o; o >>= 1) M = fmaxf(M, __shfl_xor_sync(~0u, M, o));
        float S = sl * __expf(m - M);
#pragma unroll
        for (int o = 16; o; o >>= 1) S += __shfl_xor_sync(~0u, S, o);
        if (tid == 0) { MS[0] = M; MS[1] = S; }
    }
    __syncthreads();
    const float M = MS[0];
    const float invS = 1.f / MS[1];
    if (tid < 32) scale[tid] = __expf(g_bm[b * 32 + tid] - M) * invS;
    __syncthreads();

    float acc = 0.f;
#pragma unroll
    for (int blk = 0; blk < 32; blk++)
        acc = fmaf(g_partial[(size_t)(b * 32 + blk) * EE + tid], scale[blk], acc);
    out[b * EE + tid] = acc;

    const float* sc = g_scores + (size_t)b * LL;
    float* w = attn + (size_t)b * LL;
#pragma unroll
    for (int i = 0; i < 8; i++) {
        int l = tid + i * 512;
        w[l] = __expf(sc[l] - M) * invS;
    }
}

// ---------------------------------------------------------------------------
extern "C" void kernel_launch(void* const* d_in, const int* in_sizes, int n_in,
                              void* d_out, int out_size)
{
    const float* features = (const float*)d_in[0];
    const float* dh       = (const float*)d_in[1];
    const float* W_enc    = (const float*)d_in[2];
    const float* b_enc    = (const float*)d_in[3];
    const float* W_dec    = (const float*)d_in[4];
    const float* b_dec    = (const float*)d_in[5];
    const float* W_v      = (const float*)d_in[6];
    const float* b_v      = (const float*)d_in[7];

    float* out  = (float*)d_out;        // [B,E]
    float* attn = out + BB * EE;        // [B,L]

    cudaFuncSetAttribute(score_kernel,
                         cudaFuncAttributeMaxDynamicSharedMemorySize,
                         SMEM_BYTES);

    setup_kernel<<<64, 256>>>(W_enc, dh, W_dec, b_enc, b_dec);
    score_kernel<<<(BB * LL) / 128, 512, SMEM_BYTES>>>(features, W_v, b_v);
    finalize_kernel<<<BB, 512>>>(out, attn);
}